// round 1
// baseline (speedup 1.0000x reference)
#include <cuda_runtime.h>

// Problem constants (fixed shapes for this problem)
#define N_NODES 20000
#define F_IN    8
#define T_P     12
#define HID     32
#define FEAT    96     // F_IN * T_P floats per node
#define FEAT4   24     // FEAT / 4 (float4 chunks)

// ---------------- device scratch (no allocations allowed) ----------------
__device__ float  g_deg [N_NODES];
__device__ float  g_dinv[N_NODES];
__device__ float4 g_agg [N_NODES * FEAT4];       // normalized-aggregated raw features
__device__ float  g_WLz [F_IN * HID];            // Wz @ Lz_top  (8 x 32)
__device__ float  g_WLh [F_IN * HID];            // Wh @ Lh_top  (8 x 32)
__device__ float  g_blz [HID];                   // bz @ Lz_top + lz
__device__ float  g_blh [HID];                   // bh @ Lh_top + lh
__device__ float  g_probs[T_P];                  // softmax(att)

__device__ __forceinline__ float fast_tanh(float x) {
    float y;
    asm("tanh.approx.f32 %0, %1;" : "=f"(y) : "f"(x));
    return y;
}

// ---------------- kernels ----------------

__global__ void k_init_deg() {
    int i = blockIdx.x * blockDim.x + threadIdx.x;
    if (i < N_NODES) g_deg[i] = 1.0f;              // +1 self-loop
}

__global__ void k_degree(const int* __restrict__ dst, int E) {
    int i = blockIdx.x * blockDim.x + threadIdx.x;
    if (i < E) atomicAdd(&g_deg[dst[i]], 1.0f);
}

__global__ void k_dinv() {
    int i = blockIdx.x * blockDim.x + threadIdx.x;
    if (i < N_NODES) g_dinv[i] = rsqrtf(g_deg[i]);
}

// self-loop term initializes agg fully: agg[n] = dinv[n]^2 * x[n]
__global__ void k_self(const float4* __restrict__ x4) {
    int i = blockIdx.x * blockDim.x + threadIdx.x;
    if (i >= N_NODES * FEAT4) return;
    int n = i / FEAT4;
    float d = g_dinv[n];
    float s = d * d;
    float4 v = x4[i];
    v.x *= s; v.y *= s; v.z *= s; v.w *= s;
    g_agg[i] = v;
}

// scatter: agg[dst] += dinv[src]*dinv[dst] * x[src]   (vectorized red.v4)
__global__ void k_scatter(const float4* __restrict__ x4,
                          const int* __restrict__ src,
                          const int* __restrict__ dst, int E) {
    int i = blockIdx.x * blockDim.x + threadIdx.x;
    if (i >= E * FEAT4) return;
    int e = i / FEAT4;
    int c = i - e * FEAT4;
    int s = src[e];
    int d = dst[e];
    float nrm = g_dinv[s] * g_dinv[d];
    float4 v = x4[s * FEAT4 + c];
    float4* p = &g_agg[d * FEAT4 + c];
    asm volatile("red.global.add.v4.f32 [%0], {%1, %2, %3, %4};"
                 :: "l"(p), "f"(v.x * nrm), "f"(v.y * nrm),
                    "f"(v.z * nrm), "f"(v.w * nrm)
                 : "memory");
}

// fold weights: WL = W @ L_top, bl = b @ L_top + l ; probs = softmax(att)
__global__ void k_pre(const float* __restrict__ Wz, const float* __restrict__ bz,
                      const float* __restrict__ Wh, const float* __restrict__ bh,
                      const float* __restrict__ Lz, const float* __restrict__ lz,
                      const float* __restrict__ Lh, const float* __restrict__ lh,
                      const float* __restrict__ att) {
    int tid = threadIdx.x;
    if (tid < F_IN * HID) {
        int f = tid >> 5, h = tid & 31;
        float az = 0.f, ah = 0.f;
        #pragma unroll 8
        for (int k = 0; k < HID; k++) {
            az = fmaf(Wz[f * HID + k], Lz[k * HID + h], az);
            ah = fmaf(Wh[f * HID + k], Lh[k * HID + h], ah);
        }
        g_WLz[tid] = az;
        g_WLh[tid] = ah;
    }
    if (tid < HID) {
        float az = lz[tid], ah = lh[tid];
        for (int k = 0; k < HID; k++) {
            az = fmaf(bz[k], Lz[k * HID + tid], az);
            ah = fmaf(bh[k], Lh[k * HID + tid], ah);
        }
        g_blz[tid] = az;
        g_blh[tid] = ah;
    }
    if (tid == 0) {
        float m = -1e30f;
        for (int t = 0; t < T_P; t++) m = fmaxf(m, att[t]);
        float e[T_P], s = 0.f;
        for (int t = 0; t < T_P; t++) { e[t] = __expf(att[t] - m); s += e[t]; }
        float inv = 1.0f / s;
        for (int t = 0; t < T_P; t++) g_probs[t] = e[t] * inv;
    }
}

// One warp per node: gates + attention accumulation + output projection.
__global__ void k_node(const float* __restrict__ Wout,
                       const float* __restrict__ bout,
                       float* __restrict__ out) {
    __shared__ float sh[8][FEAT];
    int w = threadIdx.x >> 5;
    int lane = threadIdx.x & 31;
    int node = blockIdx.x * 8 + w;
    if (node >= N_NODES) return;

    const float* agg = (const float*)g_agg + node * FEAT;
    sh[w][lane]      = agg[lane];
    sh[w][lane + 32] = agg[lane + 32];
    sh[w][lane + 64] = agg[lane + 64];
    __syncwarp();

    // lane == hidden index h
    float wz[F_IN], wh[F_IN];
    #pragma unroll
    for (int f = 0; f < F_IN; f++) {
        wz[f] = g_WLz[f * HID + lane];
        wh[f] = g_WLh[f * HID + lane];
    }
    float bz0 = g_blz[lane];
    float bh0 = g_blh[lane];

    float hacc = 0.f;
    #pragma unroll
    for (int t = 0; t < T_P; t++) {
        float uz = bz0, uh = bh0;
        #pragma unroll
        for (int f = 0; f < F_IN; f++) {
            float xa = sh[w][f * T_P + t];      // broadcast read
            uz = fmaf(xa, wz[f], uz);
            uh = fmaf(xa, wh[f], uh);
        }
        // (1 - sigmoid(uz)) = 0.5*(1 - tanh(uz/2))
        float omz = 0.5f - 0.5f * fast_tanh(0.5f * uz);
        float ht  = fast_tanh(uh);
        hacc = fmaf(g_probs[t], omz * ht, hacc);
    }

    __syncwarp();
    sh[w][lane] = fmaxf(hacc, 0.f);             // relu(H_accum)
    __syncwarp();

    if (lane < T_P) {
        float acc = bout[lane];
        #pragma unroll
        for (int h = 0; h < HID; h++)
            acc = fmaf(sh[w][h], Wout[h * T_P + lane], acc);
        out[node * T_P + lane] = acc;
    }
}

// ---------------- launch ----------------
extern "C" void kernel_launch(void* const* d_in, const int* in_sizes, int n_in,
                              void* d_out, int out_size) {
    const float* x    = (const float*)d_in[0];   // (N, F_IN, T)
    const int*   ei   = (const int*)  d_in[1];   // (2, E)
    const float* Wz   = (const float*)d_in[2];
    const float* bz   = (const float*)d_in[3];
    // d_in[4], d_in[5]: Wr, br  (dead: H0 == 0)
    const float* Wh   = (const float*)d_in[6];
    const float* bh   = (const float*)d_in[7];
    const float* Lz   = (const float*)d_in[8];
    const float* lz   = (const float*)d_in[9];
    // d_in[10], d_in[11]: Lr, lr (dead)
    const float* Lh   = (const float*)d_in[12];
    const float* lh   = (const float*)d_in[13];
    const float* att  = (const float*)d_in[14];
    const float* Wout = (const float*)d_in[15];
    const float* bout = (const float*)d_in[16];
    float* out = (float*)d_out;

    int E = in_sizes[1] / 2;
    const int* src = ei;
    const int* dst = ei + E;

    const float4* x4 = (const float4*)x;

    k_init_deg<<<(N_NODES + 255) / 256, 256>>>();
    k_degree  <<<(E + 255) / 256, 256>>>(dst, E);
    k_pre     <<<1, 256>>>(Wz, bz, Wh, bh, Lz, lz, Lh, lh, att);
    k_dinv    <<<(N_NODES + 255) / 256, 256>>>();
    k_self    <<<(N_NODES * FEAT4 + 255) / 256, 256>>>(x4);
    k_scatter <<<(E * FEAT4 + 255) / 256, 256>>>(x4, src, dst, E);
    k_node    <<<(N_NODES + 7) / 8, 256>>>(Wout, bout, out);
}